// round 13
// baseline (speedup 1.0000x reference)
#include <cuda_runtime.h>
#include <cuda_fp16.h>
#include <mma.h>
#include <math.h>
#include <float.h>

using namespace nvcuda;

#define NN 50000
#define EE 800000
#define ET (EE + NN)
#define CAP 128     // ELL row capacity (max degree ~45 for this fixed dataset)

#define SA_LD 136   // padded half stride (64 rows)
#define SW_LD 136   // padded half stride (128 rows)
#define SC_LD 132   // padded float stride (64 rows)
#define GEMM_SMEM (64 * SA_LD * 2 + 128 * SW_LD * 2)   // 52224 B

// ---------------- scratch ---------------------------------------------------
__device__ __half g_h1[NN * 128];
__device__ __half g_h2[NN * 128];
__device__ float  g_agg1[NN * 128];
__device__ float  g_as1[NN * 4];
__device__ float  g_ad1[NN * 4];
__device__ float  g_as2[NN];
__device__ float  g_ad2[NN];
__device__ int    g_deg[NN];          // zero at load; re-zeroed by k_node2
__device__ int2   g_ell[NN * CAP];    // (src, orig_edge_idx)
__device__ float  g_w1[ET * 4];       // per-edge exp weights (orig order), layer1
__device__ float  g_w2[ET];           // layer2

__device__ __forceinline__ float lrelu(float x) { return x > 0.f ? x : 0.2f * x; }
__device__ __forceinline__ float elu(float x)   { return x > 0.f ? x : expm1f(x); }

// ---------------- ELL build (single kernel) ---------------------------------
__global__ void k_fill(const int* __restrict__ ei) {
    int e = blockIdx.x * blockDim.x + threadIdx.x;
    if (e >= ET) return;
    int s, d;
    if (e < EE) { s = ei[e]; d = ei[EE + e]; } else { s = e - EE; d = s; }
    int pos = atomicAdd(&g_deg[d], 1);
    if (pos < CAP) g_ell[d * CAP + pos] = make_int2(s, e);
}

// ---------------- tensor-core GEMM [NN,128]@[128,128], padded smem ----------
template <int LAYER>
__global__ void __launch_bounds__(512) k_gemm_tc(const float* __restrict__ Xext,
                                                 const float* __restrict__ W,
                                                 const float* __restrict__ asrc,
                                                 const float* __restrict__ adst) {
    extern __shared__ __align__(16) char smem[];
    __half* sA = (__half*)smem;                        // 64 x SA_LD
    __half* sW = (__half*)(smem + 64 * SA_LD * 2);     // 128 x SW_LD
    float*  sC = (float*)smem;                         // 64 x SC_LD (reuse)

    const float* __restrict__ X = (LAYER == 0) ? Xext : g_agg1;
    __half* __restrict__ H = (LAYER == 0) ? g_h1 : g_h2;

    int tid = threadIdx.x;
    int row0 = blockIdx.x * 64;

    // stage W (fp32 -> fp16): 4096 float4, 8 per thread
#pragma unroll
    for (int j = 0; j < 8; j++) {
        int idx = tid + j * 512;
        int r = idx >> 5, c4 = idx & 31;
        float4 v = ((const float4*)W)[idx];
        __half2 h0 = __floats2half2_rn(v.x, v.y);
        __half2 h1 = __floats2half2_rn(v.z, v.w);
        *(__half2*)(sW + r * SW_LD + c4 * 4)     = h0;
        *(__half2*)(sW + r * SW_LD + c4 * 4 + 2) = h1;
    }
    // stage A (fp32 -> fp16): 2048 float4, 4 per thread
#pragma unroll
    for (int j = 0; j < 4; j++) {
        int idx = tid + j * 512;
        int r = idx >> 5, c4 = idx & 31;
        int row = row0 + r;
        float4 v = make_float4(0.f, 0.f, 0.f, 0.f);
        if (row < NN) v = ((const float4*)X)[row * 32 + c4];
        __half2 h0 = __floats2half2_rn(v.x, v.y);
        __half2 h1 = __floats2half2_rn(v.z, v.w);
        *(__half2*)(sA + r * SA_LD + c4 * 4)     = h0;
        *(__half2*)(sA + r * SA_LD + c4 * 4 + 2) = h1;
    }
    __syncthreads();

    int wid = tid >> 5;
    int wr = wid >> 2, wc = wid & 3;

    wmma::fragment<wmma::accumulator, 16, 16, 16, float> c0, c1;
    wmma::fill_fragment(c0, 0.f);
    wmma::fill_fragment(c1, 0.f);

#pragma unroll
    for (int k = 0; k < 8; k++) {
        wmma::fragment<wmma::matrix_a, 16, 16, 16, __half, wmma::row_major> af;
        wmma::fragment<wmma::matrix_b, 16, 16, 16, __half, wmma::row_major> bf0, bf1;
        wmma::load_matrix_sync(af, sA + wr * 16 * SA_LD + k * 16, SA_LD);
        wmma::load_matrix_sync(bf0, sW + k * 16 * SW_LD + wc * 32, SW_LD);
        wmma::load_matrix_sync(bf1, sW + k * 16 * SW_LD + wc * 32 + 16, SW_LD);
        wmma::mma_sync(c0, af, bf0, c0);
        wmma::mma_sync(c1, af, bf1, c1);
    }
    __syncthreads();

    wmma::store_matrix_sync(sC + wr * 16 * SC_LD + wc * 32,      c0, SC_LD, wmma::mem_row_major);
    wmma::store_matrix_sync(sC + wr * 16 * SC_LD + wc * 32 + 16, c1, SC_LD, wmma::mem_row_major);
    __syncthreads();

    {
        int r = tid >> 3;
        int t8 = tid & 7;
        int c0i = t8 * 16;
        int row = row0 + r;
        if (row < NN) {
            float v[16];
#pragma unroll
            for (int j = 0; j < 16; j++) v[j] = sC[r * SC_LD + c0i + j];

            __half2 hh[8];
#pragma unroll
            for (int j = 0; j < 8; j++) hh[j] = __floats2half2_rn(v[2 * j], v[2 * j + 1]);
            uint4 p0 = make_uint4(*(unsigned*)&hh[0], *(unsigned*)&hh[1], *(unsigned*)&hh[2], *(unsigned*)&hh[3]);
            uint4 p1 = make_uint4(*(unsigned*)&hh[4], *(unsigned*)&hh[5], *(unsigned*)&hh[6], *(unsigned*)&hh[7]);
            ((uint4*)H)[row * 16 + t8 * 2]     = p0;
            ((uint4*)H)[row * 16 + t8 * 2 + 1] = p1;

            float s = 0.f, d = 0.f;
#pragma unroll
            for (int j = 0; j < 16; j++) {
                s += v[j] * asrc[c0i + j];
                d += v[j] * adst[c0i + j];
            }
            if (LAYER == 0) {
                s += __shfl_xor_sync(0xffffffffu, s, 1);
                d += __shfl_xor_sync(0xffffffffu, d, 1);
                if ((t8 & 1) == 0) {
                    g_as1[row * 4 + (t8 >> 1)] = s;
                    g_ad1[row * 4 + (t8 >> 1)] = d;
                }
            } else {
#pragma unroll
                for (int off = 1; off < 8; off <<= 1) {
                    s += __shfl_xor_sync(0xffffffffu, s, off);
                    d += __shfl_xor_sync(0xffffffffu, d, off);
                }
                if (t8 == 0) { g_as2[row] = s; g_ad2[row] = d; }
            }
        }
    }
}

// ---------------- edge weights in ORIGINAL edge order (CSR-independent) -----
__global__ void k_edgew1(const int* __restrict__ ei) {
    int e = blockIdx.x * blockDim.x + threadIdx.x;
    if (e >= ET) return;
    int s, d;
    if (e < EE) { s = ei[e]; d = ei[EE + e]; } else { s = e - EE; d = s; }
    float4 a = ((const float4*)g_as1)[s];
    float4 b = ((const float4*)g_ad1)[d];
    float4 w;
    w.x = __expf(lrelu(a.x + b.x));
    w.y = __expf(lrelu(a.y + b.y));
    w.z = __expf(lrelu(a.z + b.z));
    w.w = __expf(lrelu(a.w + b.w));
    ((float4*)g_w1)[e] = w;
}

__global__ void k_edgew2(const int* __restrict__ ei) {
    int e = blockIdx.x * blockDim.x + threadIdx.x;
    if (e >= ET) return;
    int s, d;
    if (e < EE) { s = ei[e]; d = ei[EE + e]; } else { s = e - EE; d = s; }
    g_w2[e] = __expf(lrelu(g_as2[s] + g_ad2[d]));
}

// ---------------- node aggregation, layer 1 (4 heads) -----------------------
__global__ void k_node1(const float* __restrict__ b1) {
    int w = (blockIdx.x * blockDim.x + threadIdx.x) >> 5;
    int lane = threadIdx.x & 31;
    if (w >= NN) return;
    int deg = min(g_deg[w], CAP);
    const int2* __restrict__ row = &g_ell[w * CAP];
    int hd = lane >> 3;

    float ws = 0.f;
    float4 acc = make_float4(0.f, 0.f, 0.f, 0.f);

    int i = 0;
    for (; i + 4 <= deg; i += 4) {
        int2 e0 = row[i], e1 = row[i + 1], e2 = row[i + 2], e3 = row[i + 3];
        float4 w0 = ((const float4*)g_w1)[e0.y];
        float4 w1 = ((const float4*)g_w1)[e1.y];
        float4 w2 = ((const float4*)g_w1)[e2.y];
        float4 w3 = ((const float4*)g_w1)[e3.y];
        uint2 r0 = ((const uint2*)g_h1)[e0.x * 32 + lane];
        uint2 r1 = ((const uint2*)g_h1)[e1.x * 32 + lane];
        uint2 r2 = ((const uint2*)g_h1)[e2.x * 32 + lane];
        uint2 r3 = ((const uint2*)g_h1)[e3.x * 32 + lane];
        float wh0 = (hd == 0) ? w0.x : (hd == 1) ? w0.y : (hd == 2) ? w0.z : w0.w;
        float wh1 = (hd == 0) ? w1.x : (hd == 1) ? w1.y : (hd == 2) ? w1.z : w1.w;
        float wh2 = (hd == 0) ? w2.x : (hd == 1) ? w2.y : (hd == 2) ? w2.z : w2.w;
        float wh3 = (hd == 0) ? w3.x : (hd == 1) ? w3.y : (hd == 2) ? w3.z : w3.w;
        ws += wh0 + wh1 + wh2 + wh3;
        float2 a0 = __half22float2(*reinterpret_cast<__half2*>(&r0.x));
        float2 b0 = __half22float2(*reinterpret_cast<__half2*>(&r0.y));
        float2 a1 = __half22float2(*reinterpret_cast<__half2*>(&r1.x));
        float2 b1v = __half22float2(*reinterpret_cast<__half2*>(&r1.y));
        float2 a2 = __half22float2(*reinterpret_cast<__half2*>(&r2.x));
        float2 b2v = __half22float2(*reinterpret_cast<__half2*>(&r2.y));
        float2 a3 = __half22float2(*reinterpret_cast<__half2*>(&r3.x));
        float2 b3v = __half22float2(*reinterpret_cast<__half2*>(&r3.y));
        acc.x += wh0 * a0.x + wh1 * a1.x + wh2 * a2.x + wh3 * a3.x;
        acc.y += wh0 * a0.y + wh1 * a1.y + wh2 * a2.y + wh3 * a3.y;
        acc.z += wh0 * b0.x + wh1 * b1v.x + wh2 * b2v.x + wh3 * b3v.x;
        acc.w += wh0 * b0.y + wh1 * b1v.y + wh2 * b2v.y + wh3 * b3v.y;
    }
    for (; i < deg; i++) {
        int2 e0 = row[i];
        float4 wv = ((const float4*)g_w1)[e0.y];
        float wh = (hd == 0) ? wv.x : (hd == 1) ? wv.y : (hd == 2) ? wv.z : wv.w;
        ws += wh;
        uint2 raw = ((const uint2*)g_h1)[e0.x * 32 + lane];
        float2 f01 = __half22float2(*reinterpret_cast<__half2*>(&raw.x));
        float2 f23 = __half22float2(*reinterpret_cast<__half2*>(&raw.y));
        acc.x += wh * f01.x;
        acc.y += wh * f01.y;
        acc.z += wh * f23.x;
        acc.w += wh * f23.y;
    }

    float inv = 1.f / (ws + 1e-16f);
    float4 bv = ((const float4*)b1)[lane];
    float4 o;
    o.x = elu(acc.x * inv + bv.x);
    o.y = elu(acc.y * inv + bv.y);
    o.z = elu(acc.z * inv + bv.z);
    o.w = elu(acc.w * inv + bv.w);
    ((float4*)g_agg1)[w * 32 + lane] = o;
}

// ---------------- node aggregation, layer 2 (1 head); re-zeroes g_deg -------
__global__ void k_node2(const float* __restrict__ b2, float* __restrict__ out) {
    int w = (blockIdx.x * blockDim.x + threadIdx.x) >> 5;
    int lane = threadIdx.x & 31;
    if (w >= NN) return;
    int deg = min(g_deg[w], CAP);
    const int2* __restrict__ row = &g_ell[w * CAP];

    float ws = 0.f;
    float4 acc = make_float4(0.f, 0.f, 0.f, 0.f);

    int i = 0;
    for (; i + 4 <= deg; i += 4) {
        int2 e0 = row[i], e1 = row[i + 1], e2 = row[i + 2], e3 = row[i + 3];
        float w0 = g_w2[e0.y], w1 = g_w2[e1.y], w2 = g_w2[e2.y], w3 = g_w2[e3.y];
        uint2 r0 = ((const uint2*)g_h2)[e0.x * 32 + lane];
        uint2 r1 = ((const uint2*)g_h2)[e1.x * 32 + lane];
        uint2 r2 = ((const uint2*)g_h2)[e2.x * 32 + lane];
        uint2 r3 = ((const uint2*)g_h2)[e3.x * 32 + lane];
        ws += w0 + w1 + w2 + w3;
        float2 a0 = __half22float2(*reinterpret_cast<__half2*>(&r0.x));
        float2 b0 = __half22float2(*reinterpret_cast<__half2*>(&r0.y));
        float2 a1 = __half22float2(*reinterpret_cast<__half2*>(&r1.x));
        float2 b1v = __half22float2(*reinterpret_cast<__half2*>(&r1.y));
        float2 a2 = __half22float2(*reinterpret_cast<__half2*>(&r2.x));
        float2 b2v = __half22float2(*reinterpret_cast<__half2*>(&r2.y));
        float2 a3 = __half22float2(*reinterpret_cast<__half2*>(&r3.x));
        float2 b3v = __half22float2(*reinterpret_cast<__half2*>(&r3.y));
        acc.x += w0 * a0.x + w1 * a1.x + w2 * a2.x + w3 * a3.x;
        acc.y += w0 * a0.y + w1 * a1.y + w2 * a2.y + w3 * a3.y;
        acc.z += w0 * b0.x + w1 * b1v.x + w2 * b2v.x + w3 * b3v.x;
        acc.w += w0 * b0.y + w1 * b1v.y + w2 * b2v.y + w3 * b3v.y;
    }
    for (; i < deg; i++) {
        int2 e0 = row[i];
        float wv = g_w2[e0.y];
        ws += wv;
        uint2 raw = ((const uint2*)g_h2)[e0.x * 32 + lane];
        float2 f01 = __half22float2(*reinterpret_cast<__half2*>(&raw.x));
        float2 f23 = __half22float2(*reinterpret_cast<__half2*>(&raw.y));
        acc.x += wv * f01.x;
        acc.y += wv * f01.y;
        acc.z += wv * f23.x;
        acc.w += wv * f23.y;
    }

    float inv = 1.f / (ws + 1e-16f);
    float4 bv = ((const float4*)b2)[lane];
    float4 o;
    o.x = elu(acc.x * inv + bv.x);
    o.y = elu(acc.y * inv + bv.y);
    o.z = elu(acc.z * inv + bv.z);
    o.w = elu(acc.w * inv + bv.w);
    ((float4*)out)[w * 32 + lane] = o;

    if (lane == 0) g_deg[w] = 0;   // restore invariant for next launch
}

// ---------------- host launch ------------------------------------------------
extern "C" void kernel_launch(void* const* d_in, const int* in_sizes, int n_in,
                              void* d_out, int out_size) {
    const float* x    = (const float*)d_in[0];
    const int*   ei   = (const int*)  d_in[1];
    const float* W1   = (const float*)d_in[2];
    const float* a_s1 = (const float*)d_in[3];
    const float* a_d1 = (const float*)d_in[4];
    const float* b1   = (const float*)d_in[5];
    const float* W2   = (const float*)d_in[6];
    const float* a_s2 = (const float*)d_in[7];
    const float* a_d2 = (const float*)d_in[8];
    const float* b2   = (const float*)d_in[9];
    float* out = (float*)d_out;

    const int EB = (ET + 255) / 256;
    const int WARPB = (NN * 32 + 255) / 256;
    const int GB = (NN + 63) / 64;

    cudaFuncSetAttribute(k_gemm_tc<0>, cudaFuncAttributeMaxDynamicSharedMemorySize, GEMM_SMEM);
    cudaFuncSetAttribute(k_gemm_tc<1>, cudaFuncAttributeMaxDynamicSharedMemorySize, GEMM_SMEM);

    // fork: ELL build on s1 || GEMM1 + edgew1 on default stream
    cudaStream_t s1;
    cudaEvent_t evFork, evJoin;
    cudaStreamCreateWithFlags(&s1, cudaStreamNonBlocking);
    cudaEventCreateWithFlags(&evFork, cudaEventDisableTiming);
    cudaEventCreateWithFlags(&evJoin, cudaEventDisableTiming);

    cudaEventRecord(evFork, 0);
    cudaStreamWaitEvent(s1, evFork, 0);

    k_fill<<<EB, 256, 0, s1>>>(ei);
    cudaEventRecord(evJoin, s1);

    k_gemm_tc<0><<<GB, 512, GEMM_SMEM>>>(x, W1, a_s1, a_d1);
    k_edgew1<<<EB, 256>>>(ei);          // needs only alphas, not adjacency

    cudaStreamWaitEvent(0, evJoin, 0);  // join: node1 needs ELL too

    k_node1<<<WARPB, 256>>>(b1);

    k_gemm_tc<1><<<GB, 512, GEMM_SMEM>>>(nullptr, W2, a_s2, a_d2);
    k_edgew2<<<EB, 256>>>(ei);
    k_node2<<<WARPB, 256>>>(b2, out);
}

// round 14
// speedup vs baseline: 1.0040x; 1.0040x over previous
#include <cuda_runtime.h>
#include <cuda_fp16.h>
#include <mma.h>
#include <math.h>
#include <float.h>

using namespace nvcuda;

#define NN 50000
#define EE 800000
#define ET (EE + NN)
#define CAP 128     // ELL row capacity (max degree ~45 for this fixed dataset)

#define SA_LD 136   // padded half stride (64 rows)
#define SW_LD 136   // padded half stride (128 rows)
#define SC_LD 132   // padded float stride (64 rows)
#define GEMM_SMEM (64 * SA_LD * 2 + 128 * SW_LD * 2)   // 52224 B

// ---------------- scratch ---------------------------------------------------
__device__ __half g_h1[NN * 128];
__device__ __half g_h2[NN * 128];
__device__ float  g_agg1[NN * 128];
__device__ float  g_as1[NN * 4];
__device__ float  g_ad1[NN * 4];
__device__ float  g_as2[NN];
__device__ float  g_ad2[NN];
__device__ int    g_deg[NN];          // zero at load; re-zeroed by k_node2
__device__ int2   g_ell[NN * CAP];    // (src, orig_edge_idx)
__device__ float  g_w1[ET * 4];       // per-edge exp weights (orig order), layer1
__device__ float  g_w2[ET];           // layer2

__device__ __forceinline__ float lrelu(float x) { return x > 0.f ? x : 0.2f * x; }
__device__ __forceinline__ float elu(float x)   { return x > 0.f ? x : expm1f(x); }

// ---------------- ELL build (single kernel) ---------------------------------
__global__ void k_fill(const int* __restrict__ ei) {
    int e = blockIdx.x * blockDim.x + threadIdx.x;
    if (e >= ET) return;
    int s, d;
    if (e < EE) { s = ei[e]; d = ei[EE + e]; } else { s = e - EE; d = s; }
    int pos = atomicAdd(&g_deg[d], 1);
    if (pos < CAP) g_ell[d * CAP + pos] = make_int2(s, e);
}

// ---------------- tensor-core GEMM [NN,128]@[128,128], padded smem ----------
template <int LAYER>
__global__ void __launch_bounds__(512) k_gemm_tc(const float* __restrict__ Xext,
                                                 const float* __restrict__ W,
                                                 const float* __restrict__ asrc,
                                                 const float* __restrict__ adst) {
    extern __shared__ __align__(16) char smem[];
    __half* sA = (__half*)smem;                        // 64 x SA_LD
    __half* sW = (__half*)(smem + 64 * SA_LD * 2);     // 128 x SW_LD
    float*  sC = (float*)smem;                         // 64 x SC_LD (reuse)

    const float* __restrict__ X = (LAYER == 0) ? Xext : g_agg1;
    __half* __restrict__ H = (LAYER == 0) ? g_h1 : g_h2;

    int tid = threadIdx.x;
    int row0 = blockIdx.x * 64;

    // stage W (fp32 -> fp16): 4096 float4, 8 per thread
#pragma unroll
    for (int j = 0; j < 8; j++) {
        int idx = tid + j * 512;
        int r = idx >> 5, c4 = idx & 31;
        float4 v = ((const float4*)W)[idx];
        __half2 h0 = __floats2half2_rn(v.x, v.y);
        __half2 h1 = __floats2half2_rn(v.z, v.w);
        *(__half2*)(sW + r * SW_LD + c4 * 4)     = h0;
        *(__half2*)(sW + r * SW_LD + c4 * 4 + 2) = h1;
    }
    // stage A (fp32 -> fp16): 2048 float4, 4 per thread
#pragma unroll
    for (int j = 0; j < 4; j++) {
        int idx = tid + j * 512;
        int r = idx >> 5, c4 = idx & 31;
        int row = row0 + r;
        float4 v = make_float4(0.f, 0.f, 0.f, 0.f);
        if (row < NN) v = ((const float4*)X)[row * 32 + c4];
        __half2 h0 = __floats2half2_rn(v.x, v.y);
        __half2 h1 = __floats2half2_rn(v.z, v.w);
        *(__half2*)(sA + r * SA_LD + c4 * 4)     = h0;
        *(__half2*)(sA + r * SA_LD + c4 * 4 + 2) = h1;
    }
    __syncthreads();

    int wid = tid >> 5;
    int wr = wid >> 2, wc = wid & 3;

    wmma::fragment<wmma::accumulator, 16, 16, 16, float> c0, c1;
    wmma::fill_fragment(c0, 0.f);
    wmma::fill_fragment(c1, 0.f);

#pragma unroll
    for (int k = 0; k < 8; k++) {
        wmma::fragment<wmma::matrix_a, 16, 16, 16, __half, wmma::row_major> af;
        wmma::fragment<wmma::matrix_b, 16, 16, 16, __half, wmma::row_major> bf0, bf1;
        wmma::load_matrix_sync(af, sA + wr * 16 * SA_LD + k * 16, SA_LD);
        wmma::load_matrix_sync(bf0, sW + k * 16 * SW_LD + wc * 32, SW_LD);
        wmma::load_matrix_sync(bf1, sW + k * 16 * SW_LD + wc * 32 + 16, SW_LD);
        wmma::mma_sync(c0, af, bf0, c0);
        wmma::mma_sync(c1, af, bf1, c1);
    }
    __syncthreads();

    wmma::store_matrix_sync(sC + wr * 16 * SC_LD + wc * 32,      c0, SC_LD, wmma::mem_row_major);
    wmma::store_matrix_sync(sC + wr * 16 * SC_LD + wc * 32 + 16, c1, SC_LD, wmma::mem_row_major);
    __syncthreads();

    {
        int r = tid >> 3;
        int t8 = tid & 7;
        int c0i = t8 * 16;
        int row = row0 + r;
        if (row < NN) {
            float v[16];
#pragma unroll
            for (int j = 0; j < 16; j++) v[j] = sC[r * SC_LD + c0i + j];

            __half2 hh[8];
#pragma unroll
            for (int j = 0; j < 8; j++) hh[j] = __floats2half2_rn(v[2 * j], v[2 * j + 1]);
            uint4 p0 = make_uint4(*(unsigned*)&hh[0], *(unsigned*)&hh[1], *(unsigned*)&hh[2], *(unsigned*)&hh[3]);
            uint4 p1 = make_uint4(*(unsigned*)&hh[4], *(unsigned*)&hh[5], *(unsigned*)&hh[6], *(unsigned*)&hh[7]);
            ((uint4*)H)[row * 16 + t8 * 2]     = p0;
            ((uint4*)H)[row * 16 + t8 * 2 + 1] = p1;

            float s = 0.f, d = 0.f;
#pragma unroll
            for (int j = 0; j < 16; j++) {
                s += v[j] * asrc[c0i + j];
                d += v[j] * adst[c0i + j];
            }
            if (LAYER == 0) {
                s += __shfl_xor_sync(0xffffffffu, s, 1);
                d += __shfl_xor_sync(0xffffffffu, d, 1);
                if ((t8 & 1) == 0) {
                    g_as1[row * 4 + (t8 >> 1)] = s;
                    g_ad1[row * 4 + (t8 >> 1)] = d;
                }
            } else {
#pragma unroll
                for (int off = 1; off < 8; off <<= 1) {
                    s += __shfl_xor_sync(0xffffffffu, s, off);
                    d += __shfl_xor_sync(0xffffffffu, d, off);
                }
                if (t8 == 0) { g_as2[row] = s; g_ad2[row] = d; }
            }
        }
    }
}

// ---------------- edge weights in ORIGINAL edge order (CSR-independent) -----
__global__ void k_edgew1(const int* __restrict__ ei) {
    int e = blockIdx.x * blockDim.x + threadIdx.x;
    if (e >= ET) return;
    int s, d;
    if (e < EE) { s = ei[e]; d = ei[EE + e]; } else { s = e - EE; d = s; }
    float4 a = ((const float4*)g_as1)[s];
    float4 b = ((const float4*)g_ad1)[d];
    float4 w;
    w.x = __expf(lrelu(a.x + b.x));
    w.y = __expf(lrelu(a.y + b.y));
    w.z = __expf(lrelu(a.z + b.z));
    w.w = __expf(lrelu(a.w + b.w));
    ((float4*)g_w1)[e] = w;
}

__global__ void k_edgew2(const int* __restrict__ ei) {
    int e = blockIdx.x * blockDim.x + threadIdx.x;
    if (e >= ET) return;
    int s, d;
    if (e < EE) { s = ei[e]; d = ei[EE + e]; } else { s = e - EE; d = s; }
    g_w2[e] = __expf(lrelu(g_as2[s] + g_ad2[d]));
}

// ---------------- node aggregation, layer 1 (4 heads) -----------------------
__global__ void k_node1(const float* __restrict__ b1) {
    int w = (blockIdx.x * blockDim.x + threadIdx.x) >> 5;
    int lane = threadIdx.x & 31;
    if (w >= NN) return;
    int deg = min(g_deg[w], CAP);
    const int2* __restrict__ row = &g_ell[w * CAP];
    int hd = lane >> 3;

    float ws = 0.f;
    float4 acc = make_float4(0.f, 0.f, 0.f, 0.f);

    int i = 0;
    for (; i + 4 <= deg; i += 4) {
        int2 e0 = row[i], e1 = row[i + 1], e2 = row[i + 2], e3 = row[i + 3];
        float4 w0 = ((const float4*)g_w1)[e0.y];
        float4 w1 = ((const float4*)g_w1)[e1.y];
        float4 w2 = ((const float4*)g_w1)[e2.y];
        float4 w3 = ((const float4*)g_w1)[e3.y];
        uint2 r0 = ((const uint2*)g_h1)[e0.x * 32 + lane];
        uint2 r1 = ((const uint2*)g_h1)[e1.x * 32 + lane];
        uint2 r2 = ((const uint2*)g_h1)[e2.x * 32 + lane];
        uint2 r3 = ((const uint2*)g_h1)[e3.x * 32 + lane];
        float wh0 = (hd == 0) ? w0.x : (hd == 1) ? w0.y : (hd == 2) ? w0.z : w0.w;
        float wh1 = (hd == 0) ? w1.x : (hd == 1) ? w1.y : (hd == 2) ? w1.z : w1.w;
        float wh2 = (hd == 0) ? w2.x : (hd == 1) ? w2.y : (hd == 2) ? w2.z : w2.w;
        float wh3 = (hd == 0) ? w3.x : (hd == 1) ? w3.y : (hd == 2) ? w3.z : w3.w;
        ws += wh0 + wh1 + wh2 + wh3;
        float2 a0 = __half22float2(*reinterpret_cast<__half2*>(&r0.x));
        float2 b0 = __half22float2(*reinterpret_cast<__half2*>(&r0.y));
        float2 a1 = __half22float2(*reinterpret_cast<__half2*>(&r1.x));
        float2 b1v = __half22float2(*reinterpret_cast<__half2*>(&r1.y));
        float2 a2 = __half22float2(*reinterpret_cast<__half2*>(&r2.x));
        float2 b2v = __half22float2(*reinterpret_cast<__half2*>(&r2.y));
        float2 a3 = __half22float2(*reinterpret_cast<__half2*>(&r3.x));
        float2 b3v = __half22float2(*reinterpret_cast<__half2*>(&r3.y));
        acc.x += wh0 * a0.x + wh1 * a1.x + wh2 * a2.x + wh3 * a3.x;
        acc.y += wh0 * a0.y + wh1 * a1.y + wh2 * a2.y + wh3 * a3.y;
        acc.z += wh0 * b0.x + wh1 * b1v.x + wh2 * b2v.x + wh3 * b3v.x;
        acc.w += wh0 * b0.y + wh1 * b1v.y + wh2 * b2v.y + wh3 * b3v.y;
    }
    for (; i < deg; i++) {
        int2 e0 = row[i];
        float4 wv = ((const float4*)g_w1)[e0.y];
        float wh = (hd == 0) ? wv.x : (hd == 1) ? wv.y : (hd == 2) ? wv.z : wv.w;
        ws += wh;
        uint2 raw = ((const uint2*)g_h1)[e0.x * 32 + lane];
        float2 f01 = __half22float2(*reinterpret_cast<__half2*>(&raw.x));
        float2 f23 = __half22float2(*reinterpret_cast<__half2*>(&raw.y));
        acc.x += wh * f01.x;
        acc.y += wh * f01.y;
        acc.z += wh * f23.x;
        acc.w += wh * f23.y;
    }

    float inv = 1.f / (ws + 1e-16f);
    float4 bv = ((const float4*)b1)[lane];
    float4 o;
    o.x = elu(acc.x * inv + bv.x);
    o.y = elu(acc.y * inv + bv.y);
    o.z = elu(acc.z * inv + bv.z);
    o.w = elu(acc.w * inv + bv.w);
    ((float4*)g_agg1)[w * 32 + lane] = o;
}

// ---------------- node aggregation, layer 2 (1 head); re-zeroes g_deg -------
__global__ void k_node2(const float* __restrict__ b2, float* __restrict__ out) {
    int w = (blockIdx.x * blockDim.x + threadIdx.x) >> 5;
    int lane = threadIdx.x & 31;
    if (w >= NN) return;
    int deg = min(g_deg[w], CAP);
    const int2* __restrict__ row = &g_ell[w * CAP];

    float ws = 0.f;
    float4 acc = make_float4(0.f, 0.f, 0.f, 0.f);

    int i = 0;
    for (; i + 4 <= deg; i += 4) {
        int2 e0 = row[i], e1 = row[i + 1], e2 = row[i + 2], e3 = row[i + 3];
        float w0 = g_w2[e0.y], w1 = g_w2[e1.y], w2 = g_w2[e2.y], w3 = g_w2[e3.y];
        uint2 r0 = ((const uint2*)g_h2)[e0.x * 32 + lane];
        uint2 r1 = ((const uint2*)g_h2)[e1.x * 32 + lane];
        uint2 r2 = ((const uint2*)g_h2)[e2.x * 32 + lane];
        uint2 r3 = ((const uint2*)g_h2)[e3.x * 32 + lane];
        ws += w0 + w1 + w2 + w3;
        float2 a0 = __half22float2(*reinterpret_cast<__half2*>(&r0.x));
        float2 b0 = __half22float2(*reinterpret_cast<__half2*>(&r0.y));
        float2 a1 = __half22float2(*reinterpret_cast<__half2*>(&r1.x));
        float2 b1v = __half22float2(*reinterpret_cast<__half2*>(&r1.y));
        float2 a2 = __half22float2(*reinterpret_cast<__half2*>(&r2.x));
        float2 b2v = __half22float2(*reinterpret_cast<__half2*>(&r2.y));
        float2 a3 = __half22float2(*reinterpret_cast<__half2*>(&r3.x));
        float2 b3v = __half22float2(*reinterpret_cast<__half2*>(&r3.y));
        acc.x += w0 * a0.x + w1 * a1.x + w2 * a2.x + w3 * a3.x;
        acc.y += w0 * a0.y + w1 * a1.y + w2 * a2.y + w3 * a3.y;
        acc.z += w0 * b0.x + w1 * b1v.x + w2 * b2v.x + w3 * b3v.x;
        acc.w += w0 * b0.y + w1 * b1v.y + w2 * b2v.y + w3 * b3v.y;
    }
    for (; i < deg; i++) {
        int2 e0 = row[i];
        float wv = g_w2[e0.y];
        ws += wv;
        uint2 raw = ((const uint2*)g_h2)[e0.x * 32 + lane];
        float2 f01 = __half22float2(*reinterpret_cast<__half2*>(&raw.x));
        float2 f23 = __half22float2(*reinterpret_cast<__half2*>(&raw.y));
        acc.x += wv * f01.x;
        acc.y += wv * f01.y;
        acc.z += wv * f23.x;
        acc.w += wv * f23.y;
    }

    float inv = 1.f / (ws + 1e-16f);
    float4 bv = ((const float4*)b2)[lane];
    float4 o;
    o.x = elu(acc.x * inv + bv.x);
    o.y = elu(acc.y * inv + bv.y);
    o.z = elu(acc.z * inv + bv.z);
    o.w = elu(acc.w * inv + bv.w);
    ((float4*)out)[w * 32 + lane] = o;

    if (lane == 0) g_deg[w] = 0;   // restore invariant for next launch
}

// ---------------- host launch ------------------------------------------------
extern "C" void kernel_launch(void* const* d_in, const int* in_sizes, int n_in,
                              void* d_out, int out_size) {
    const float* x    = (const float*)d_in[0];
    const int*   ei   = (const int*)  d_in[1];
    const float* W1   = (const float*)d_in[2];
    const float* a_s1 = (const float*)d_in[3];
    const float* a_d1 = (const float*)d_in[4];
    const float* b1   = (const float*)d_in[5];
    const float* W2   = (const float*)d_in[6];
    const float* a_s2 = (const float*)d_in[7];
    const float* a_d2 = (const float*)d_in[8];
    const float* b2   = (const float*)d_in[9];
    float* out = (float*)d_out;

    const int EB = (ET + 255) / 256;
    const int WARPB = (NN * 32 + 255) / 256;
    const int GB = (NN + 63) / 64;

    cudaFuncSetAttribute(k_gemm_tc<0>, cudaFuncAttributeMaxDynamicSharedMemorySize, GEMM_SMEM);
    cudaFuncSetAttribute(k_gemm_tc<1>, cudaFuncAttributeMaxDynamicSharedMemorySize, GEMM_SMEM);

    // fork: ELL build on s1 || GEMM1 + edgew1 on default stream
    cudaStream_t s1;
    cudaEvent_t evFork, evJoin;
    cudaStreamCreateWithFlags(&s1, cudaStreamNonBlocking);
    cudaEventCreateWithFlags(&evFork, cudaEventDisableTiming);
    cudaEventCreateWithFlags(&evJoin, cudaEventDisableTiming);

    cudaEventRecord(evFork, 0);
    cudaStreamWaitEvent(s1, evFork, 0);

    k_fill<<<EB, 256, 0, s1>>>(ei);
    cudaEventRecord(evJoin, s1);

    k_gemm_tc<0><<<GB, 512, GEMM_SMEM>>>(x, W1, a_s1, a_d1);
    k_edgew1<<<EB, 256>>>(ei);          // needs only alphas, not adjacency

    cudaStreamWaitEvent(0, evJoin, 0);  // join: node1 needs ELL too

    k_node1<<<WARPB, 256>>>(b1);

    k_gemm_tc<1><<<GB, 512, GEMM_SMEM>>>(nullptr, W2, a_s2, a_d2);
    k_edgew2<<<EB, 256>>>(ei);
    k_node2<<<WARPB, 256>>>(b2, out);
}

// round 15
// speedup vs baseline: 1.1169x; 1.1125x over previous
#include <cuda_runtime.h>
#include <cuda_fp16.h>
#include <mma.h>
#include <math.h>
#include <float.h>

using namespace nvcuda;

#define NN 50000
#define EE 800000
#define ET (EE + NN)
#define SCAN_B 49   // ceil(50000/1024)

#define SA_LD 136   // padded half stride (64 rows)
#define SW_LD 136   // padded half stride (128 rows)
#define SC_LD 132   // padded float stride (64 rows)
#define GEMM_SMEM (64 * SA_LD * 2 + 128 * SW_LD * 2)   // 52224 B

// ---------------- scratch ---------------------------------------------------
__device__ __half g_h1[NN * 128];
__device__ __half g_h2[NN * 128];
__device__ float  g_agg1[NN * 128];
__device__ float  g_as1[NN * 4];
__device__ float  g_ad1[NN * 4];
__device__ float  g_as2[NN];
__device__ float  g_ad2[NN];
__device__ int    g_deg[NN];           // zero at load; re-zeroed by k_scan_part
__device__ int    g_scan[SCAN_B * 1024];   // inclusive within block
__device__ int    g_scan2[SCAN_B * 1024];  // exclusive within block
__device__ int    g_bsum[SCAN_B];
__device__ int    g_rowptr[NN + 1];
__device__ int    g_fill[NN];
__device__ int2   g_cd[ET];            // packed (src, dst), CSR order
__device__ float  g_w1[4 * ET];        // per-edge exp weights, HEAD-MAJOR, CSR order
__device__ float  g_w2[ET];            // layer2, CSR order

__device__ __forceinline__ float lrelu(float x) { return x > 0.f ? x : 0.2f * x; }
__device__ __forceinline__ float elu(float x)   { return x > 0.f ? x : expm1f(x); }

// ---------------- CSR build -------------------------------------------------
__global__ void k_count(const int* __restrict__ ei) {
    int e = blockIdx.x * blockDim.x + threadIdx.x;
    if (e >= ET) return;
    int d = (e < EE) ? ei[EE + e] : (e - EE);
    atomicAdd(&g_deg[d], 1);
}

// per-1024 block scan; also re-zeroes g_deg (maintains deg==0 invariant)
__global__ void k_scan_part() {
    __shared__ int sh[1024];
    int tid = threadIdx.x;
    int i = blockIdx.x * 1024 + tid;
    int v = (i < NN) ? g_deg[i] : 0;
    sh[tid] = v;
    __syncthreads();
#pragma unroll
    for (int off = 1; off < 1024; off <<= 1) {
        int t = (tid >= off) ? sh[tid - off] : 0;
        __syncthreads();
        sh[tid] += t;
        __syncthreads();
    }
    g_scan[i]  = sh[tid];
    g_scan2[i] = sh[tid] - v;
    if (i < NN) g_deg[i] = 0;
    if (tid == 1023) g_bsum[blockIdx.x] = sh[tid];
}

// rowptr + fill-base; block-local redundant top-level prefix over g_bsum
__global__ void k_rowptr() {
    __shared__ int sb[SCAN_B + 1];
    int t = threadIdx.x;
    if (t < SCAN_B) sb[t + 1] = g_bsum[t];
    __syncthreads();
    if (t == 0) {
        sb[0] = 0;
        for (int b = 1; b < SCAN_B; b++) sb[b] += sb[b - 1];
    }
    __syncthreads();
    int i = blockIdx.x * blockDim.x + t;
    if (i >= NN) return;
    int boff = sb[i >> 10];
    g_rowptr[i + 1] = g_scan[i] + boff;
    g_fill[i] = g_scan2[i] + boff;
    if (i == 0) g_rowptr[0] = 0;
}

__global__ void k_fill(const int* __restrict__ ei) {
    int e = blockIdx.x * blockDim.x + threadIdx.x;
    if (e >= ET) return;
    int s, d;
    if (e < EE) { s = ei[e]; d = ei[EE + e]; } else { s = e - EE; d = s; }
    int pos = atomicAdd(&g_fill[d], 1);
    g_cd[pos] = make_int2(s, d);
}

// ---------------- tensor-core GEMM [NN,128]@[128,128], padded smem ----------
template <int LAYER>
__global__ void __launch_bounds__(512) k_gemm_tc(const float* __restrict__ Xext,
                                                 const float* __restrict__ W,
                                                 const float* __restrict__ asrc,
                                                 const float* __restrict__ adst) {
    extern __shared__ __align__(16) char smem[];
    __half* sA = (__half*)smem;                        // 64 x SA_LD
    __half* sW = (__half*)(smem + 64 * SA_LD * 2);     // 128 x SW_LD
    float*  sC = (float*)smem;                         // 64 x SC_LD (reuse)

    const float* __restrict__ X = (LAYER == 0) ? Xext : g_agg1;
    __half* __restrict__ H = (LAYER == 0) ? g_h1 : g_h2;

    int tid = threadIdx.x;
    int row0 = blockIdx.x * 64;

    // stage W (fp32 -> fp16): 4096 float4, 8 per thread
#pragma unroll
    for (int j = 0; j < 8; j++) {
        int idx = tid + j * 512;
        int r = idx >> 5, c4 = idx & 31;
        float4 v = ((const float4*)W)[idx];
        __half2 h0 = __floats2half2_rn(v.x, v.y);
        __half2 h1 = __floats2half2_rn(v.z, v.w);
        *(__half2*)(sW + r * SW_LD + c4 * 4)     = h0;
        *(__half2*)(sW + r * SW_LD + c4 * 4 + 2) = h1;
    }
    // stage A (fp32 -> fp16): 2048 float4, 4 per thread
#pragma unroll
    for (int j = 0; j < 4; j++) {
        int idx = tid + j * 512;
        int r = idx >> 5, c4 = idx & 31;
        int row = row0 + r;
        float4 v = make_float4(0.f, 0.f, 0.f, 0.f);
        if (row < NN) v = ((const float4*)X)[row * 32 + c4];
        __half2 h0 = __floats2half2_rn(v.x, v.y);
        __half2 h1 = __floats2half2_rn(v.z, v.w);
        *(__half2*)(sA + r * SA_LD + c4 * 4)     = h0;
        *(__half2*)(sA + r * SA_LD + c4 * 4 + 2) = h1;
    }
    __syncthreads();

    int wid = tid >> 5;
    int wr = wid >> 2, wc = wid & 3;

    wmma::fragment<wmma::accumulator, 16, 16, 16, float> c0, c1;
    wmma::fill_fragment(c0, 0.f);
    wmma::fill_fragment(c1, 0.f);

#pragma unroll
    for (int k = 0; k < 8; k++) {
        wmma::fragment<wmma::matrix_a, 16, 16, 16, __half, wmma::row_major> af;
        wmma::fragment<wmma::matrix_b, 16, 16, 16, __half, wmma::row_major> bf0, bf1;
        wmma::load_matrix_sync(af, sA + wr * 16 * SA_LD + k * 16, SA_LD);
        wmma::load_matrix_sync(bf0, sW + k * 16 * SW_LD + wc * 32, SW_LD);
        wmma::load_matrix_sync(bf1, sW + k * 16 * SW_LD + wc * 32 + 16, SW_LD);
        wmma::mma_sync(c0, af, bf0, c0);
        wmma::mma_sync(c1, af, bf1, c1);
    }
    __syncthreads();

    wmma::store_matrix_sync(sC + wr * 16 * SC_LD + wc * 32,      c0, SC_LD, wmma::mem_row_major);
    wmma::store_matrix_sync(sC + wr * 16 * SC_LD + wc * 32 + 16, c1, SC_LD, wmma::mem_row_major);
    __syncthreads();

    {
        int r = tid >> 3;
        int t8 = tid & 7;
        int c0i = t8 * 16;
        int row = row0 + r;
        if (row < NN) {
            float v[16];
#pragma unroll
            for (int j = 0; j < 16; j++) v[j] = sC[r * SC_LD + c0i + j];

            __half2 hh[8];
#pragma unroll
            for (int j = 0; j < 8; j++) hh[j] = __floats2half2_rn(v[2 * j], v[2 * j + 1]);
            uint4 p0 = make_uint4(*(unsigned*)&hh[0], *(unsigned*)&hh[1], *(unsigned*)&hh[2], *(unsigned*)&hh[3]);
            uint4 p1 = make_uint4(*(unsigned*)&hh[4], *(unsigned*)&hh[5], *(unsigned*)&hh[6], *(unsigned*)&hh[7]);
            ((uint4*)H)[row * 16 + t8 * 2]     = p0;
            ((uint4*)H)[row * 16 + t8 * 2 + 1] = p1;

            float s = 0.f, d = 0.f;
#pragma unroll
            for (int j = 0; j < 16; j++) {
                s += v[j] * asrc[c0i + j];
                d += v[j] * adst[c0i + j];
            }
            if (LAYER == 0) {
                s += __shfl_xor_sync(0xffffffffu, s, 1);
                d += __shfl_xor_sync(0xffffffffu, d, 1);
                if ((t8 & 1) == 0) {
                    g_as1[row * 4 + (t8 >> 1)] = s;
                    g_ad1[row * 4 + (t8 >> 1)] = d;
                }
            } else {
#pragma unroll
                for (int off = 1; off < 8; off <<= 1) {
                    s += __shfl_xor_sync(0xffffffffu, s, off);
                    d += __shfl_xor_sync(0xffffffffu, d, off);
                }
                if (t8 == 0) { g_as2[row] = s; g_ad2[row] = d; }
            }
        }
    }
}

// ---------------- edge-parallel exp weights (CSR order, head-major) ---------
__global__ void k_edgew1() {
    int e = blockIdx.x * blockDim.x + threadIdx.x;
    if (e >= ET) return;
    int2 cd = g_cd[e];
    float4 a = ((const float4*)g_as1)[cd.x];
    float4 b = ((const float4*)g_ad1)[cd.y];
    g_w1[0 * ET + e] = __expf(lrelu(a.x + b.x));
    g_w1[1 * ET + e] = __expf(lrelu(a.y + b.y));
    g_w1[2 * ET + e] = __expf(lrelu(a.z + b.z));
    g_w1[3 * ET + e] = __expf(lrelu(a.w + b.w));
}

__global__ void k_edgew2() {
    int e = blockIdx.x * blockDim.x + threadIdx.x;
    if (e >= ET) return;
    int2 cd = g_cd[e];
    g_w2[e] = __expf(lrelu(g_as2[cd.x] + g_ad2[cd.y]));
}

// ---------------- node aggregation, layer 1 (4 heads) -----------------------
// warp per node; lane owns 4 channels; head weight read as scalar (head-major)
__global__ void k_node1(const float* __restrict__ b1) {
    int w = (blockIdx.x * blockDim.x + threadIdx.x) >> 5;
    int lane = threadIdx.x & 31;
    if (w >= NN) return;
    int beg = g_rowptr[w], end = g_rowptr[w + 1];
    const float* __restrict__ wh_base = g_w1 + (lane >> 3) * ET;

    float ws = 0.f;
    float4 acc = make_float4(0.f, 0.f, 0.f, 0.f);

    int i = beg;
    for (; i + 4 <= end; i += 4) {
        int s0 = g_cd[i].x, s1 = g_cd[i + 1].x, s2 = g_cd[i + 2].x, s3 = g_cd[i + 3].x;
        float wh0 = wh_base[i];
        float wh1 = wh_base[i + 1];
        float wh2 = wh_base[i + 2];
        float wh3 = wh_base[i + 3];
        uint2 r0 = ((const uint2*)g_h1)[s0 * 32 + lane];
        uint2 r1 = ((const uint2*)g_h1)[s1 * 32 + lane];
        uint2 r2 = ((const uint2*)g_h1)[s2 * 32 + lane];
        uint2 r3 = ((const uint2*)g_h1)[s3 * 32 + lane];
        ws += wh0 + wh1 + wh2 + wh3;
        float2 a0 = __half22float2(*reinterpret_cast<__half2*>(&r0.x));
        float2 b0 = __half22float2(*reinterpret_cast<__half2*>(&r0.y));
        float2 a1 = __half22float2(*reinterpret_cast<__half2*>(&r1.x));
        float2 b1v = __half22float2(*reinterpret_cast<__half2*>(&r1.y));
        float2 a2 = __half22float2(*reinterpret_cast<__half2*>(&r2.x));
        float2 b2v = __half22float2(*reinterpret_cast<__half2*>(&r2.y));
        float2 a3 = __half22float2(*reinterpret_cast<__half2*>(&r3.x));
        float2 b3v = __half22float2(*reinterpret_cast<__half2*>(&r3.y));
        acc.x += wh0 * a0.x + wh1 * a1.x + wh2 * a2.x + wh3 * a3.x;
        acc.y += wh0 * a0.y + wh1 * a1.y + wh2 * a2.y + wh3 * a3.y;
        acc.z += wh0 * b0.x + wh1 * b1v.x + wh2 * b2v.x + wh3 * b3v.x;
        acc.w += wh0 * b0.y + wh1 * b1v.y + wh2 * b2v.y + wh3 * b3v.y;
    }
    for (; i < end; i++) {
        int s = g_cd[i].x;
        float wh = wh_base[i];
        ws += wh;
        uint2 raw = ((const uint2*)g_h1)[s * 32 + lane];
        float2 f01 = __half22float2(*reinterpret_cast<__half2*>(&raw.x));
        float2 f23 = __half22float2(*reinterpret_cast<__half2*>(&raw.y));
        acc.x += wh * f01.x;
        acc.y += wh * f01.y;
        acc.z += wh * f23.x;
        acc.w += wh * f23.y;
    }

    float inv = 1.f / (ws + 1e-16f);
    float4 bv = ((const float4*)b1)[lane];
    float4 o;
    o.x = elu(acc.x * inv + bv.x);
    o.y = elu(acc.y * inv + bv.y);
    o.z = elu(acc.z * inv + bv.z);
    o.w = elu(acc.w * inv + bv.w);
    ((float4*)g_agg1)[w * 32 + lane] = o;
}

// ---------------- node aggregation, layer 2 (1 head) ------------------------
__global__ void k_node2(const float* __restrict__ b2, float* __restrict__ out) {
    int w = (blockIdx.x * blockDim.x + threadIdx.x) >> 5;
    int lane = threadIdx.x & 31;
    if (w >= NN) return;
    int beg = g_rowptr[w], end = g_rowptr[w + 1];

    float ws = 0.f;
    float4 acc = make_float4(0.f, 0.f, 0.f, 0.f);

    int i = beg;
    for (; i + 4 <= end; i += 4) {
        int s0 = g_cd[i].x, s1 = g_cd[i + 1].x, s2 = g_cd[i + 2].x, s3 = g_cd[i + 3].x;
        float w0 = g_w2[i], w1 = g_w2[i + 1], w2 = g_w2[i + 2], w3 = g_w2[i + 3];
        uint2 r0 = ((const uint2*)g_h2)[s0 * 32 + lane];
        uint2 r1 = ((const uint2*)g_h2)[s1 * 32 + lane];
        uint2 r2 = ((const uint2*)g_h2)[s2 * 32 + lane];
        uint2 r3 = ((const uint2*)g_h2)[s3 * 32 + lane];
        ws += w0 + w1 + w2 + w3;
        float2 a0 = __half22float2(*reinterpret_cast<__half2*>(&r0.x));
        float2 b0 = __half22float2(*reinterpret_cast<__half2*>(&r0.y));
        float2 a1 = __half22float2(*reinterpret_cast<__half2*>(&r1.x));
        float2 b1v = __half22float2(*reinterpret_cast<__half2*>(&r1.y));
        float2 a2 = __half22float2(*reinterpret_cast<__half2*>(&r2.x));
        float2 b2v = __half22float2(*reinterpret_cast<__half2*>(&r2.y));
        float2 a3 = __half22float2(*reinterpret_cast<__half2*>(&r3.x));
        float2 b3v = __half22float2(*reinterpret_cast<__half2*>(&r3.y));
        acc.x += w0 * a0.x + w1 * a1.x + w2 * a2.x + w3 * a3.x;
        acc.y += w0 * a0.y + w1 * a1.y + w2 * a2.y + w3 * a3.y;
        acc.z += w0 * b0.x + w1 * b1v.x + w2 * b2v.x + w3 * b3v.x;
        acc.w += w0 * b0.y + w1 * b1v.y + w2 * b2v.y + w3 * b3v.y;
    }
    for (; i < end; i++) {
        int s = g_cd[i].x;
        float wv = g_w2[i];
        ws += wv;
        uint2 raw = ((const uint2*)g_h2)[s * 32 + lane];
        float2 f01 = __half22float2(*reinterpret_cast<__half2*>(&raw.x));
        float2 f23 = __half22float2(*reinterpret_cast<__half2*>(&raw.y));
        acc.x += wv * f01.x;
        acc.y += wv * f01.y;
        acc.z += wv * f23.x;
        acc.w += wv * f23.y;
    }

    float inv = 1.f / (ws + 1e-16f);
    float4 bv = ((const float4*)b2)[lane];
    float4 o;
    o.x = elu(acc.x * inv + bv.x);
    o.y = elu(acc.y * inv + bv.y);
    o.z = elu(acc.z * inv + bv.z);
    o.w = elu(acc.w * inv + bv.w);
    ((float4*)out)[w * 32 + lane] = o;
}

// ---------------- host launch ------------------------------------------------
extern "C" void kernel_launch(void* const* d_in, const int* in_sizes, int n_in,
                              void* d_out, int out_size) {
    const float* x    = (const float*)d_in[0];
    const int*   ei   = (const int*)  d_in[1];
    const float* W1   = (const float*)d_in[2];
    const float* a_s1 = (const float*)d_in[3];
    const float* a_d1 = (const float*)d_in[4];
    const float* b1   = (const float*)d_in[5];
    const float* W2   = (const float*)d_in[6];
    const float* a_s2 = (const float*)d_in[7];
    const float* a_d2 = (const float*)d_in[8];
    const float* b2   = (const float*)d_in[9];
    float* out = (float*)d_out;

    const int EB = (ET + 255) / 256;
    const int NB = (NN + 255) / 256;
    const int WARPB = (NN * 32 + 255) / 256;
    const int GB = (NN + 63) / 64;

    cudaFuncSetAttribute(k_gemm_tc<0>, cudaFuncAttributeMaxDynamicSharedMemorySize, GEMM_SMEM);
    cudaFuncSetAttribute(k_gemm_tc<1>, cudaFuncAttributeMaxDynamicSharedMemorySize, GEMM_SMEM);

    // fork: CSR build on s1, GEMM1 on default stream
    cudaStream_t s1;
    cudaEvent_t evFork, evJoin;
    cudaStreamCreateWithFlags(&s1, cudaStreamNonBlocking);
    cudaEventCreateWithFlags(&evFork, cudaEventDisableTiming);
    cudaEventCreateWithFlags(&evJoin, cudaEventDisableTiming);

    cudaEventRecord(evFork, 0);
    cudaStreamWaitEvent(s1, evFork, 0);

    // CSR chain on s1 (g_deg zeroed invariant: load-time + re-zero in scan_part)
    k_count<<<EB, 256, 0, s1>>>(ei);
    k_scan_part<<<SCAN_B, 1024, 0, s1>>>();
    k_rowptr<<<NB, 256, 0, s1>>>();
    k_fill<<<EB, 256, 0, s1>>>(ei);
    cudaEventRecord(evJoin, s1);

    // GEMM1 on default stream (independent of CSR)
    k_gemm_tc<0><<<GB, 512, GEMM_SMEM>>>(x, W1, a_s1, a_d1);

    // join
    cudaStreamWaitEvent(0, evJoin, 0);

    k_edgew1<<<EB, 256>>>();
    k_node1<<<WARPB, 256>>>(b1);

    k_gemm_tc<1><<<GB, 512, GEMM_SMEM>>>(nullptr, W2, a_s2, a_d2);
    k_edgew2<<<EB, 256>>>();
    k_node2<<<WARPB, 256>>>(b2, out);
}

// round 16
// speedup vs baseline: 1.1326x; 1.0141x over previous
#include <cuda_runtime.h>
#include <cuda_fp16.h>
#include <mma.h>
#include <math.h>
#include <float.h>

using namespace nvcuda;

#define NN 50000
#define EE 800000
#define ET (EE + NN)
#define SCAN_B 49   // ceil(50000/1024)

#define SA_LD 136
#define SW_LD 136
#define SC_LD 132
#define GEMM_SMEM (64 * SA_LD * 2 + 128 * SW_LD * 2)   // 52224 B

// ---------------- scratch ---------------------------------------------------
__device__ __half g_h1[NN * 128];
__device__ __half g_h2[NN * 128];
__device__ float  g_agg1[NN * 128];
__device__ float  g_as1[NN * 4];
__device__ float  g_ad1[NN * 4];
__device__ float  g_as2[NN];
__device__ float  g_ad2[NN];
__device__ int    g_deg[NN];           // zero at load; re-zeroed by k_scan_part
__device__ int    g_scan[SCAN_B * 1024];
__device__ int    g_scan2[SCAN_B * 1024];
__device__ int    g_bsum[SCAN_B];
__device__ int    g_rowptr[NN + 1];
__device__ int    g_fill[NN];
__device__ int2   g_cd[ET];            // packed (src, dst), CSR order
__device__ float  g_w1[4 * ET];        // exp weights, HEAD-MAJOR, CSR order
__device__ float  g_w2[ET];            // layer2, CSR order

__device__ __forceinline__ float lrelu(float x) { return x > 0.f ? x : 0.2f * x; }
__device__ __forceinline__ float elu(float x)   { return x > 0.f ? x : expm1f(x); }

// ---------------- CSR build -------------------------------------------------
__global__ void k_count(const int* __restrict__ ei) {
    int e = blockIdx.x * blockDim.x + threadIdx.x;
    if (e >= ET) return;
    int d = (e < EE) ? ei[EE + e] : (e - EE);
    atomicAdd(&g_deg[d], 1);
}

__global__ void k_scan_part() {
    __shared__ int sh[1024];
    int tid = threadIdx.x;
    int i = blockIdx.x * 1024 + tid;
    int v = (i < NN) ? g_deg[i] : 0;
    sh[tid] = v;
    __syncthreads();
#pragma unroll
    for (int off = 1; off < 1024; off <<= 1) {
        int t = (tid >= off) ? sh[tid - off] : 0;
        __syncthreads();
        sh[tid] += t;
        __syncthreads();
    }
    g_scan[i]  = sh[tid];
    g_scan2[i] = sh[tid] - v;
    if (i < NN) g_deg[i] = 0;
    if (tid == 1023) g_bsum[blockIdx.x] = sh[tid];
}

__global__ void k_rowptr() {
    __shared__ int sb[SCAN_B + 1];
    int t = threadIdx.x;
    if (t < SCAN_B) sb[t + 1] = g_bsum[t];
    __syncthreads();
    if (t == 0) {
        sb[0] = 0;
        for (int b = 1; b < SCAN_B; b++) sb[b] += sb[b - 1];
    }
    __syncthreads();
    int i = blockIdx.x * blockDim.x + t;
    if (i >= NN) return;
    int boff = sb[i >> 10];
    g_rowptr[i + 1] = g_scan[i] + boff;
    g_fill[i] = g_scan2[i] + boff;
    if (i == 0) g_rowptr[0] = 0;
}

// fill a sub-range of edges [lo, hi) — two instances run on two streams
__global__ void k_fill(const int* __restrict__ ei, int lo, int hi) {
    int e = lo + blockIdx.x * blockDim.x + threadIdx.x;
    if (e >= hi) return;
    int s, d;
    if (e < EE) { s = ei[e]; d = ei[EE + e]; } else { s = e - EE; d = s; }
    int pos = atomicAdd(&g_fill[d], 1);
    g_cd[pos] = make_int2(s, d);
}

// ---------------- tensor-core GEMM [NN,128]@[128,128], padded smem ----------
template <int LAYER>
__global__ void __launch_bounds__(512) k_gemm_tc(const float* __restrict__ Xext,
                                                 const float* __restrict__ W,
                                                 const float* __restrict__ asrc,
                                                 const float* __restrict__ adst) {
    extern __shared__ __align__(16) char smem[];
    __half* sA = (__half*)smem;
    __half* sW = (__half*)(smem + 64 * SA_LD * 2);
    float*  sC = (float*)smem;

    const float* __restrict__ X = (LAYER == 0) ? Xext : g_agg1;
    __half* __restrict__ H = (LAYER == 0) ? g_h1 : g_h2;

    int tid = threadIdx.x;
    int row0 = blockIdx.x * 64;

#pragma unroll
    for (int j = 0; j < 8; j++) {
        int idx = tid + j * 512;
        int r = idx >> 5, c4 = idx & 31;
        float4 v = ((const float4*)W)[idx];
        __half2 h0 = __floats2half2_rn(v.x, v.y);
        __half2 h1 = __floats2half2_rn(v.z, v.w);
        *(__half2*)(sW + r * SW_LD + c4 * 4)     = h0;
        *(__half2*)(sW + r * SW_LD + c4 * 4 + 2) = h1;
    }
#pragma unroll
    for (int j = 0; j < 4; j++) {
        int idx = tid + j * 512;
        int r = idx >> 5, c4 = idx & 31;
        int row = row0 + r;
        float4 v = make_float4(0.f, 0.f, 0.f, 0.f);
        if (row < NN) v = ((const float4*)X)[row * 32 + c4];
        __half2 h0 = __floats2half2_rn(v.x, v.y);
        __half2 h1 = __floats2half2_rn(v.z, v.w);
        *(__half2*)(sA + r * SA_LD + c4 * 4)     = h0;
        *(__half2*)(sA + r * SA_LD + c4 * 4 + 2) = h1;
    }
    __syncthreads();

    int wid = tid >> 5;
    int wr = wid >> 2, wc = wid & 3;

    wmma::fragment<wmma::accumulator, 16, 16, 16, float> c0, c1;
    wmma::fill_fragment(c0, 0.f);
    wmma::fill_fragment(c1, 0.f);

#pragma unroll
    for (int k = 0; k < 8; k++) {
        wmma::fragment<wmma::matrix_a, 16, 16, 16, __half, wmma::row_major> af;
        wmma::fragment<wmma::matrix_b, 16, 16, 16, __half, wmma::row_major> bf0, bf1;
        wmma::load_matrix_sync(af, sA + wr * 16 * SA_LD + k * 16, SA_LD);
        wmma::load_matrix_sync(bf0, sW + k * 16 * SW_LD + wc * 32, SW_LD);
        wmma::load_matrix_sync(bf1, sW + k * 16 * SW_LD + wc * 32 + 16, SW_LD);
        wmma::mma_sync(c0, af, bf0, c0);
        wmma::mma_sync(c1, af, bf1, c1);
    }
    __syncthreads();

    wmma::store_matrix_sync(sC + wr * 16 * SC_LD + wc * 32,      c0, SC_LD, wmma::mem_row_major);
    wmma::store_matrix_sync(sC + wr * 16 * SC_LD + wc * 32 + 16, c1, SC_LD, wmma::mem_row_major);
    __syncthreads();

    {
        int r = tid >> 3;
        int t8 = tid & 7;
        int c0i = t8 * 16;
        int row = row0 + r;
        if (row < NN) {
            float v[16];
#pragma unroll
            for (int j = 0; j < 16; j++) v[j] = sC[r * SC_LD + c0i + j];

            __half2 hh[8];
#pragma unroll
            for (int j = 0; j < 8; j++) hh[j] = __floats2half2_rn(v[2 * j], v[2 * j + 1]);
            uint4 p0 = make_uint4(*(unsigned*)&hh[0], *(unsigned*)&hh[1], *(unsigned*)&hh[2], *(unsigned*)&hh[3]);
            uint4 p1 = make_uint4(*(unsigned*)&hh[4], *(unsigned*)&hh[5], *(unsigned*)&hh[6], *(unsigned*)&hh[7]);
            ((uint4*)H)[row * 16 + t8 * 2]     = p0;
            ((uint4*)H)[row * 16 + t8 * 2 + 1] = p1;

            float s = 0.f, d = 0.f;
#pragma unroll
            for (int j = 0; j < 16; j++) {
                s += v[j] * asrc[c0i + j];
                d += v[j] * adst[c0i + j];
            }
            if (LAYER == 0) {
                s += __shfl_xor_sync(0xffffffffu, s, 1);
                d += __shfl_xor_sync(0xffffffffu, d, 1);
                if ((t8 & 1) == 0) {
                    g_as1[row * 4 + (t8 >> 1)] = s;
                    g_ad1[row * 4 + (t8 >> 1)] = d;
                }
            } else {
#pragma unroll
                for (int off = 1; off < 8; off <<= 1) {
                    s += __shfl_xor_sync(0xffffffffu, s, off);
                    d += __shfl_xor_sync(0xffffffffu, d, off);
                }
                if (t8 == 0) { g_as2[row] = s; g_ad2[row] = d; }
            }
        }
    }
}

// ---------------- edge-parallel exp weights (CSR order, head-major) ---------
__global__ void k_edgew1() {
    int e = blockIdx.x * blockDim.x + threadIdx.x;
    if (e >= ET) return;
    int2 cd = g_cd[e];
    float4 a = ((const float4*)g_as1)[cd.x];
    float4 b = ((const float4*)g_ad1)[cd.y];
    g_w1[0 * ET + e] = __expf(lrelu(a.x + b.x));
    g_w1[1 * ET + e] = __expf(lrelu(a.y + b.y));
    g_w1[2 * ET + e] = __expf(lrelu(a.z + b.z));
    g_w1[3 * ET + e] = __expf(lrelu(a.w + b.w));
}

__global__ void k_edgew2() {
    int e = blockIdx.x * blockDim.x + threadIdx.x;
    if (e >= ET) return;
    int2 cd = g_cd[e];
    g_w2[e] = __expf(lrelu(g_as2[cd.x] + g_ad2[cd.y]));
}

// ---------------- node aggregation, layer 1 (4 heads), 8x unroll ------------
__global__ void k_node1(const float* __restrict__ b1) {
    int w = (blockIdx.x * blockDim.x + threadIdx.x) >> 5;
    int lane = threadIdx.x & 31;
    if (w >= NN) return;
    int beg = g_rowptr[w], end = g_rowptr[w + 1];
    const float* __restrict__ wh_base = g_w1 + (lane >> 3) * ET;

    float ws = 0.f;
    float4 acc = make_float4(0.f, 0.f, 0.f, 0.f);

    int i = beg;
    for (; i + 8 <= end; i += 8) {
        int   ss[8];
        float wv[8];
        uint2 rr[8];
#pragma unroll
        for (int j = 0; j < 8; j++) { ss[j] = g_cd[i + j].x; wv[j] = wh_base[i + j]; }
#pragma unroll
        for (int j = 0; j < 8; j++) rr[j] = ((const uint2*)g_h1)[ss[j] * 32 + lane];
#pragma unroll
        for (int j = 0; j < 8; j++) {
            ws += wv[j];
            float2 f01 = __half22float2(*reinterpret_cast<__half2*>(&rr[j].x));
            float2 f23 = __half22float2(*reinterpret_cast<__half2*>(&rr[j].y));
            acc.x += wv[j] * f01.x;
            acc.y += wv[j] * f01.y;
            acc.z += wv[j] * f23.x;
            acc.w += wv[j] * f23.y;
        }
    }
    for (; i + 4 <= end; i += 4) {
        int   ss[4];
        float wv[4];
        uint2 rr[4];
#pragma unroll
        for (int j = 0; j < 4; j++) { ss[j] = g_cd[i + j].x; wv[j] = wh_base[i + j]; }
#pragma unroll
        for (int j = 0; j < 4; j++) rr[j] = ((const uint2*)g_h1)[ss[j] * 32 + lane];
#pragma unroll
        for (int j = 0; j < 4; j++) {
            ws += wv[j];
            float2 f01 = __half22float2(*reinterpret_cast<__half2*>(&rr[j].x));
            float2 f23 = __half22float2(*reinterpret_cast<__half2*>(&rr[j].y));
            acc.x += wv[j] * f01.x;
            acc.y += wv[j] * f01.y;
            acc.z += wv[j] * f23.x;
            acc.w += wv[j] * f23.y;
        }
    }
    for (; i < end; i++) {
        int s = g_cd[i].x;
        float wh = wh_base[i];
        ws += wh;
        uint2 raw = ((const uint2*)g_h1)[s * 32 + lane];
        float2 f01 = __half22float2(*reinterpret_cast<__half2*>(&raw.x));
        float2 f23 = __half22float2(*reinterpret_cast<__half2*>(&raw.y));
        acc.x += wh * f01.x;
        acc.y += wh * f01.y;
        acc.z += wh * f23.x;
        acc.w += wh * f23.y;
    }

    float inv = 1.f / (ws + 1e-16f);
    float4 bv = ((const float4*)b1)[lane];
    float4 o;
    o.x = elu(acc.x * inv + bv.x);
    o.y = elu(acc.y * inv + bv.y);
    o.z = elu(acc.z * inv + bv.z);
    o.w = elu(acc.w * inv + bv.w);
    ((float4*)g_agg1)[w * 32 + lane] = o;
}

// ---------------- node aggregation, layer 2 (1 head), 8x unroll --------------
__global__ void k_node2(const float* __restrict__ b2, float* __restrict__ out) {
    int w = (blockIdx.x * blockDim.x + threadIdx.x) >> 5;
    int lane = threadIdx.x & 31;
    if (w >= NN) return;
    int beg = g_rowptr[w], end = g_rowptr[w + 1];

    float ws = 0.f;
    float4 acc = make_float4(0.f, 0.f, 0.f, 0.f);

    int i = beg;
    for (; i + 8 <= end; i += 8) {
        int   ss[8];
        float wv[8];
        uint2 rr[8];
#pragma unroll
        for (int j = 0; j < 8; j++) { ss[j] = g_cd[i + j].x; wv[j] = g_w2[i + j]; }
#pragma unroll
        for (int j = 0; j < 8; j++) rr[j] = ((const uint2*)g_h2)[ss[j] * 32 + lane];
#pragma unroll
        for (int j = 0; j < 8; j++) {
            ws += wv[j];
            float2 f01 = __half22float2(*reinterpret_cast<__half2*>(&rr[j].x));
            float2 f23 = __half22float2(*reinterpret_cast<__half2*>(&rr[j].y));
            acc.x += wv[j] * f01.x;
            acc.y += wv[j] * f01.y;
            acc.z += wv[j] * f23.x;
            acc.w += wv[j] * f23.y;
        }
    }
    for (; i + 4 <= end; i += 4) {
        int   ss[4];
        float wv[4];
        uint2 rr[4];
#pragma unroll
        for (int j = 0; j < 4; j++) { ss[j] = g_cd[i + j].x; wv[j] = g_w2[i + j]; }
#pragma unroll
        for (int j = 0; j < 4; j++) rr[j] = ((const uint2*)g_h2)[ss[j] * 32 + lane];
#pragma unroll
        for (int j = 0; j < 4; j++) {
            ws += wv[j];
            float2 f01 = __half22float2(*reinterpret_cast<__half2*>(&rr[j].x));
            float2 f23 = __half22float2(*reinterpret_cast<__half2*>(&rr[j].y));
            acc.x += wv[j] * f01.x;
            acc.y += wv[j] * f01.y;
            acc.z += wv[j] * f23.x;
            acc.w += wv[j] * f23.y;
        }
    }
    for (; i < end; i++) {
        int s = g_cd[i].x;
        float wv = g_w2[i];
        ws += wv;
        uint2 raw = ((const uint2*)g_h2)[s * 32 + lane];
        float2 f01 = __half22float2(*reinterpret_cast<__half2*>(&raw.x));
        float2 f23 = __half22float2(*reinterpret_cast<__half2*>(&raw.y));
        acc.x += wv * f01.x;
        acc.y += wv * f01.y;
        acc.z += wv * f23.x;
        acc.w += wv * f23.y;
    }

    float inv = 1.f / (ws + 1e-16f);
    float4 bv = ((const float4*)b2)[lane];
    float4 o;
    o.x = elu(acc.x * inv + bv.x);
    o.y = elu(acc.y * inv + bv.y);
    o.z = elu(acc.z * inv + bv.z);
    o.w = elu(acc.w * inv + bv.w);
    ((float4*)out)[w * 32 + lane] = o;
}

// ---------------- host launch ------------------------------------------------
extern "C" void kernel_launch(void* const* d_in, const int* in_sizes, int n_in,
                              void* d_out, int out_size) {
    const float* x    = (const float*)d_in[0];
    const int*   ei   = (const int*)  d_in[1];
    const float* W1   = (const float*)d_in[2];
    const float* a_s1 = (const float*)d_in[3];
    const float* a_d1 = (const float*)d_in[4];
    const float* b1   = (const float*)d_in[5];
    const float* W2   = (const float*)d_in[6];
    const float* a_s2 = (const float*)d_in[7];
    const float* a_d2 = (const float*)d_in[8];
    const float* b2   = (const float*)d_in[9];
    float* out = (float*)d_out;

    const int EB = (ET + 255) / 256;
    const int NB = (NN + 255) / 256;
    const int WARPB = (NN * 32 + 255) / 256;
    const int GB = (NN + 63) / 64;
    const int HALF = ET / 2;
    const int FB = (HALF + 255) / 256;
    const int FB2 = (ET - HALF + 255) / 256;

    cudaFuncSetAttribute(k_gemm_tc<0>, cudaFuncAttributeMaxDynamicSharedMemorySize, GEMM_SMEM);
    cudaFuncSetAttribute(k_gemm_tc<1>, cudaFuncAttributeMaxDynamicSharedMemorySize, GEMM_SMEM);

    cudaStream_t s1;
    cudaEvent_t evFork, evCsr, evJoin;
    cudaStreamCreateWithFlags(&s1, cudaStreamNonBlocking);
    cudaEventCreateWithFlags(&evFork, cudaEventDisableTiming);
    cudaEventCreateWithFlags(&evCsr,  cudaEventDisableTiming);
    cudaEventCreateWithFlags(&evJoin, cudaEventDisableTiming);

    cudaEventRecord(evFork, 0);
    cudaStreamWaitEvent(s1, evFork, 0);

    // leg A (s1): count -> scan -> rowptr -> fill half [0, HALF)
    k_count<<<EB, 256, 0, s1>>>(ei);
    k_scan_part<<<SCAN_B, 1024, 0, s1>>>();
    k_rowptr<<<NB, 256, 0, s1>>>();
    cudaEventRecord(evCsr, s1);
    k_fill<<<FB, 256, 0, s1>>>(ei, 0, HALF);
    cudaEventRecord(evJoin, s1);

    // leg B (default): GEMM1, then fill half [HALF, ET) once rowptr is ready
    k_gemm_tc<0><<<GB, 512, GEMM_SMEM>>>(x, W1, a_s1, a_d1);
    cudaStreamWaitEvent(0, evCsr, 0);
    k_fill<<<FB2, 256>>>(ei, HALF, ET);

    // join: both fill halves done
    cudaStreamWaitEvent(0, evJoin, 0);

    k_edgew1<<<EB, 256>>>();
    k_node1<<<WARPB, 256>>>(b1);

    k_gemm_tc<1><<<GB, 512, GEMM_SMEM>>>(nullptr, W2, a_s2, a_d2);
    k_edgew2<<<EB, 256>>>();
    k_node2<<<WARPB, 256>>>(b2, out);
}